// round 15
// baseline (speedup 1.0000x reference)
#include <cuda_runtime.h>

#define HH 512
#define WW 512
#define BB 16
#define HW (HH * WW)
#define RPB 2
#define GRIDX (HH / RPB)          // 256 strips per image
#define NTILES (GRIDX * BB)       // 4096 tiles
#define NPERS  (148 * 9)          // persistent blocks = SMs * blocks/SM
#define NTHR  128
#define FULLM 0xffffffffu

__device__ __forceinline__ float ex2f(float x) {
    float r; asm("ex2.approx.f32 %0, %1;" : "=f"(r) : "f"(x)); return r;
}

// acc += (ex2(d2*C2E)*wxy - eps) * (ya-yb)^2   [mul + fma tail]
__device__ __forceinline__ void shift_term(float& acc,
                                           float a0, float a1, float a2,
                                           float b0, float b1, float b2,
                                           float ya, float yb, float wxy) {
    const float C2E = -32.059889797532520f;   // -log2(e)/(2*0.15^2)
    float dx0 = a0 - b0, dx1 = a1 - b1, dx2 = a2 - b2;
    float d2 = dx0 * dx0;
    d2 = fmaf(dx1, dx1, d2);
    d2 = fmaf(dx2, dx2, d2);
    float e = ex2f(d2 * C2E);
    float m = fmaf(e, wxy, -0.01f);           // SUB_EPS
    float dy = ya - yb;
    float t = m * dy;
    acc = fmaf(t, dy, acc);
}

__global__ void __launch_bounds__(NTHR, 9)
crf_loss_kernel(const float* __restrict__ ypr,
                const float* __restrict__ img,
                const int*   __restrict__ icls,
                float* __restrict__ out)
{
    const int tid  = threadIdx.x;
    const int lane = tid & 31;
    const int w0   = tid << 2;                 // 4 px/thread, 128 thr = full row

    const bool lastLane  = (lane == 31);
    const bool firstLane = (lane == 0);
    const bool hasR = (w0 + 4 < WW);           // false only tid 127
    const bool hasL = (w0 > 0);                // false only tid 0

    const float WXY1 = 0.60653065971263342f;   // exp(-0.5)
    const float WXY2 = 0.36787944117144233f;   // exp(-1.0)

    float acc = 0.0f;

    // persistent grid-stride over tiles; tile t -> batch b = t>>8, strip bx = t&255
    for (int t = blockIdx.x; t < NTILES; t += NPERS) {
        const int b  = t >> 8;
        const int bx = t & (GRIDX - 1);
        if (icls[b] == 0) continue;            // dead batch: skip cheaply

        const int r0 = bx * RPB;
        const float* Y = ypr + (size_t)(2 * b + 1) * HW;
        const float* I = img + (size_t)(3 * b)     * HW;   // planes +0,+HW,+2HW

        // ---- prologue: row r0 + right halo ----
        float cy[4], ca[4], cb[4], cc[4];
        float cyR, caR, cbR, ccR;
        {
            const int off = r0 * WW + w0;
            float4 q;
            q = *(const float4*)(Y + off);          cy[0]=q.x; cy[1]=q.y; cy[2]=q.z; cy[3]=q.w;
            q = *(const float4*)(I + off);          ca[0]=q.x; ca[1]=q.y; ca[2]=q.z; ca[3]=q.w;
            q = *(const float4*)(I + off + HW);     cb[0]=q.x; cb[1]=q.y; cb[2]=q.z; cb[3]=q.w;
            q = *(const float4*)(I + off + 2*HW);   cc[0]=q.x; cc[1]=q.y; cc[2]=q.z; cc[3]=q.w;
            cyR = __shfl_down_sync(FULLM, cy[0], 1);
            caR = __shfl_down_sync(FULLM, ca[0], 1);
            cbR = __shfl_down_sync(FULLM, cb[0], 1);
            ccR = __shfl_down_sync(FULLM, cc[0], 1);
            if (lastLane && hasR) {
                cyR = Y[off + 4];
                caR = I[off + 4];
                cbR = I[off + 4 + HW];
                ccR = I[off + 4 + 2*HW];
            }
        }

#pragma unroll
        for (int rr = 0; rr < RPB; rr++) {
            const int r = r0 + rr;
            const bool haveDown = (r + 1 < HH);    // uniform across block
            const int off = (r + 1) * WW + w0;

            // ---- STEP 1: issue all next-row loads ----
            float ny[4], na[4], nb[4], nc[4];
            if (haveDown) {
                float4 q;
                q = *(const float4*)(Y + off);        ny[0]=q.x; ny[1]=q.y; ny[2]=q.z; ny[3]=q.w;
                q = *(const float4*)(I + off);        na[0]=q.x; na[1]=q.y; na[2]=q.z; na[3]=q.w;
                q = *(const float4*)(I + off + HW);   nb[0]=q.x; nb[1]=q.y; nb[2]=q.z; nb[3]=q.w;
                q = *(const float4*)(I + off + 2*HW); nc[0]=q.x; nc[1]=q.y; nc[2]=q.z; nc[3]=q.w;
            } else {
#pragma unroll
                for (int k = 0; k < 4; k++) { ny[k]=0.f; na[k]=0.f; nb[k]=0.f; nc[k]=0.f; }
            }

            // ---- STEP 2: horizontal shift (0,1) on CURRENT row (independent) ----
#pragma unroll
            for (int k = 0; k < 3; k++)
                shift_term(acc, ca[k], cb[k], cc[k],
                           ca[k+1], cb[k+1], cc[k+1],
                           cy[k], cy[k+1], WXY1);
            if (hasR)
                shift_term(acc, ca[3], cb[3], cc[3], caR, cbR, ccR,
                           cy[3], cyR, WXY1);

            float nyR = 0.f, naR = 0.f, nbR = 0.f, ncR = 0.f;
            if (haveDown) {
                // ---- STEP 3: halo shuffles; edges as predicated overwrites ----
                nyR = __shfl_down_sync(FULLM, ny[0], 1);
                naR = __shfl_down_sync(FULLM, na[0], 1);
                nbR = __shfl_down_sync(FULLM, nb[0], 1);
                ncR = __shfl_down_sync(FULLM, nc[0], 1);
                float nyL = __shfl_up_sync(FULLM, ny[3], 1);
                float naL = __shfl_up_sync(FULLM, na[3], 1);
                float nbL = __shfl_up_sync(FULLM, nb[3], 1);
                float ncL = __shfl_up_sync(FULLM, nc[3], 1);
                if (lastLane && hasR) {
                    nyR = Y[off + 4];
                    naR = I[off + 4];
                    nbR = I[off + 4 + HW];
                    ncR = I[off + 4 + 2*HW];
                }
                if (firstLane && hasL) {
                    nyL = Y[off - 1];
                    naL = I[off - 1];
                    nbL = I[off - 1 + HW];
                    ncL = I[off - 1 + 2*HW];
                }

                // ---- STEP 4: vertical terms ----
                // shift (1,0)
#pragma unroll
                for (int k = 0; k < 4; k++)
                    shift_term(acc, ca[k], cb[k], cc[k],
                               na[k], nb[k], nc[k],
                               cy[k], ny[k], WXY1);
                // shift (1,1)
#pragma unroll
                for (int k = 0; k < 3; k++)
                    shift_term(acc, ca[k], cb[k], cc[k],
                               na[k+1], nb[k+1], nc[k+1],
                               cy[k], ny[k+1], WXY2);
                if (hasR)
                    shift_term(acc, ca[3], cb[3], cc[3], naR, nbR, ncR,
                               cy[3], nyR, WXY2);
                // shift (1,-1)
#pragma unroll
                for (int k = 1; k < 4; k++)
                    shift_term(acc, ca[k], cb[k], cc[k],
                               na[k-1], nb[k-1], nc[k-1],
                               cy[k], ny[k-1], WXY2);
                if (hasL)
                    shift_term(acc, ca[0], cb[0], cc[0], naL, nbL, ncL,
                               cy[0], nyL, WXY2);
            }

            // ---- roll next -> current ----
#pragma unroll
            for (int k = 0; k < 4; k++) { cy[k]=ny[k]; ca[k]=na[k]; cb[k]=nb[k]; cc[k]=nc[k]; }
            cyR = nyR; caR = naR; cbR = nbR; ccR = ncR;
        }
    }

    // ---- ONE block reduction + atomic per persistent block ----
#pragma unroll
    for (int o = 16; o > 0; o >>= 1)
        acc += __shfl_down_sync(FULLM, acc, o);

    __shared__ float sm[NTHR / 32];
    if (lane == 0) sm[tid >> 5] = acc;
    __syncthreads();
    if (tid == 0) {
        float v = sm[0] + sm[1] + sm[2] + sm[3];
        const float SCALE = 1.0f / 16777216.0f;    // 1/(H*W*B*4), WEIGHT=1
        atomicAdd(out, v * SCALE);
    }
}

__global__ void zero_out_kernel(float* out) {
    if (threadIdx.x == 0) out[0] = 0.0f;
}

extern "C" void kernel_launch(void* const* d_in, const int* in_sizes, int n_in,
                              void* d_out, int out_size) {
    const float* ypr  = (const float*)d_in[0];   // y_pr  (16,2,512,512)
    // d_in[1] = y_gt (unused by the reference)
    const float* img  = (const float*)d_in[2];   // image (16,3,512,512)
    const int*   icls = (const int*)d_in[3];     // image_class (16,)
    float* out = (float*)d_out;

    zero_out_kernel<<<1, 32>>>(out);
    crf_loss_kernel<<<NPERS, NTHR>>>(ypr, img, icls, out);
}

// round 16
// speedup vs baseline: 1.1601x; 1.1601x over previous
#include <cuda_runtime.h>

#define HH 512
#define WW 512
#define BB 16
#define HW (HH * WW)
#define RPB 2
#define GRIDX (HH / RPB)      // 256
#define NTHR  128
#define FULLM 0xffffffffu

__device__ __forceinline__ float ex2f(float x) {
    float r; asm("ex2.approx.f32 %0, %1;" : "=f"(r) : "f"(x)); return r;
}

// acc += (ex2(d2*C2E)*wxy - eps) * (ya-yb)^2   [mul + fma tail]
__device__ __forceinline__ void shift_term(float& acc,
                                           float a0, float a1, float a2,
                                           float b0, float b1, float b2,
                                           float ya, float yb, float wxy) {
    const float C2E = -32.059889797532520f;   // -log2(e)/(2*0.15^2)
    float dx0 = a0 - b0, dx1 = a1 - b1, dx2 = a2 - b2;
    float d2 = dx0 * dx0;
    d2 = fmaf(dx1, dx1, d2);
    d2 = fmaf(dx2, dx2, d2);
    float e = ex2f(d2 * C2E);
    float m = fmaf(e, wxy, -0.01f);           // SUB_EPS
    float dy = ya - yb;
    float t = m * dy;
    acc = fmaf(t, dy, acc);
}

__global__ void __launch_bounds__(NTHR, 9)
crf_loss_kernel(const float* __restrict__ ypr,
                const float* __restrict__ img,
                const int*   __restrict__ icls,
                float* __restrict__ out)
{
    const int b = blockIdx.y;
    if (icls[b] == 0) return;                  // sel == 0: no contribution

    const int tid  = threadIdx.x;
    const int lane = tid & 31;
    const int w0   = tid << 2;                 // 4 px/thread, 128 thr = full row
    const int r0   = blockIdx.x * RPB;

    const float* Y = ypr + (size_t)(2 * b + 1) * HW;
    const float* I = img + (size_t)(3 * b)     * HW;   // planes +0, +HW, +2*HW

    const bool lastLane = (lane == 31);
    const bool hasR = (w0 + 4 < WW);           // false only tid 127

    const float WXY1 = 0.60653065971263342f;   // exp(-0.5)
    const float WXY2 = 0.36787944117144233f;   // exp(-1.0)

    // ---- prologue: row r0 + right halo ----
    float cy[4], ca[4], cb[4], cc[4];
    float cyR, caR, cbR, ccR;
    {
        const int off = r0 * WW + w0;
        float4 t;
        t = *(const float4*)(Y + off);          cy[0]=t.x; cy[1]=t.y; cy[2]=t.z; cy[3]=t.w;
        t = *(const float4*)(I + off);          ca[0]=t.x; ca[1]=t.y; ca[2]=t.z; ca[3]=t.w;
        t = *(const float4*)(I + off + HW);     cb[0]=t.x; cb[1]=t.y; cb[2]=t.z; cb[3]=t.w;
        t = *(const float4*)(I + off + 2*HW);   cc[0]=t.x; cc[1]=t.y; cc[2]=t.z; cc[3]=t.w;
        cyR = __shfl_down_sync(FULLM, cy[0], 1);
        caR = __shfl_down_sync(FULLM, ca[0], 1);
        cbR = __shfl_down_sync(FULLM, cb[0], 1);
        ccR = __shfl_down_sync(FULLM, cc[0], 1);
        if (lastLane && hasR) {
            cyR = Y[off + 4];
            caR = I[off + 4];
            cbR = I[off + 4 + HW];
            ccR = I[off + 4 + 2*HW];
        }
    }

    float acc = 0.0f;

#pragma unroll
    for (int rr = 0; rr < RPB; rr++) {
        const int r = r0 + rr;
        const bool haveDown = (r + 1 < HH);    // uniform across block
        const int off = (r + 1) * WW + w0;

        // ---- STEP 1: issue all next-row loads ----
        float ny[4], na[4], nb[4], nc[4];
        if (haveDown) {
            float4 t;
            t = *(const float4*)(Y + off);        ny[0]=t.x; ny[1]=t.y; ny[2]=t.z; ny[3]=t.w;
            t = *(const float4*)(I + off);        na[0]=t.x; na[1]=t.y; na[2]=t.z; na[3]=t.w;
            t = *(const float4*)(I + off + HW);   nb[0]=t.x; nb[1]=t.y; nb[2]=t.z; nb[3]=t.w;
            t = *(const float4*)(I + off + 2*HW); nc[0]=t.x; nc[1]=t.y; nc[2]=t.z; nc[3]=t.w;
        } else {
#pragma unroll
            for (int k = 0; k < 4; k++) { ny[k]=0.f; na[k]=0.f; nb[k]=0.f; nc[k]=0.f; }
        }

        // ---- STEP 2: horizontal shift (0,1) on CURRENT row (independent) ----
#pragma unroll
        for (int k = 0; k < 3; k++)
            shift_term(acc, ca[k], cb[k], cc[k],
                       ca[k+1], cb[k+1], cc[k+1],
                       cy[k], cy[k+1], WXY1);
        if (hasR)
            shift_term(acc, ca[3], cb[3], cc[3], caR, cbR, ccR,
                       cy[3], cyR, WXY1);

        float nyR = 0.f, naR = 0.f, nbR = 0.f, ncR = 0.f;
        if (haveDown) {
            // ---- STEP 3: down-shuffles only (right halos of next row) ----
            nyR = __shfl_down_sync(FULLM, ny[0], 1);
            naR = __shfl_down_sync(FULLM, na[0], 1);
            nbR = __shfl_down_sync(FULLM, nb[0], 1);
            ncR = __shfl_down_sync(FULLM, nc[0], 1);
            if (lastLane && hasR) {
                nyR = Y[off + 4];
                naR = I[off + 4];
                nbR = I[off + 4 + HW];
                ncR = I[off + 4 + 2*HW];
            }

            // ---- STEP 4: vertical terms ----
            // shift (1,0)
#pragma unroll
            for (int k = 0; k < 4; k++)
                shift_term(acc, ca[k], cb[k], cc[k],
                           na[k], nb[k], nc[k],
                           cy[k], ny[k], WXY1);
            // shift (1,1)
#pragma unroll
            for (int k = 0; k < 3; k++)
                shift_term(acc, ca[k], cb[k], cc[k],
                           na[k+1], nb[k+1], nc[k+1],
                           cy[k], ny[k+1], WXY2);
            if (hasR)
                shift_term(acc, ca[3], cb[3], cc[3], naR, nbR, ncR,
                           cy[3], nyR, WXY2);
            // shift (1,-1): interior pairs (own data)
#pragma unroll
            for (int k = 1; k < 4; k++)
                shift_term(acc, ca[k], cb[k], cc[k],
                           na[k-1], nb[k-1], nc[k-1],
                           cy[k], ny[k-1], WXY2);
            // shift (1,-1) boundary pair (cur[w0+4], next[w0+3]) reassigned to
            // THIS lane: cur halo (c*R) vs own n*[3]. No up-shuffles needed.
            if (hasR)
                shift_term(acc, caR, cbR, ccR,
                           na[3], nb[3], nc[3],
                           cyR, ny[3], WXY2);
        }

        // ---- roll next -> current ----
#pragma unroll
        for (int k = 0; k < 4; k++) { cy[k]=ny[k]; ca[k]=na[k]; cb[k]=nb[k]; cc[k]=nc[k]; }
        cyR = nyR; caR = naR; cbR = nbR; ccR = ncR;
    }

    // ---- block reduction ----
#pragma unroll
    for (int o = 16; o > 0; o >>= 1)
        acc += __shfl_down_sync(FULLM, acc, o);

    __shared__ float sm[NTHR / 32];
    if (lane == 0) sm[tid >> 5] = acc;
    __syncthreads();
    if (tid == 0) {
        float v = sm[0] + sm[1] + sm[2] + sm[3];
        const float SCALE = 1.0f / 16777216.0f;    // 1/(H*W*B*4), WEIGHT=1
        atomicAdd(out, v * SCALE);
    }
}

__global__ void zero_out_kernel(float* out) {
    if (threadIdx.x == 0) out[0] = 0.0f;
}

extern "C" void kernel_launch(void* const* d_in, const int* in_sizes, int n_in,
                              void* d_out, int out_size) {
    const float* ypr  = (const float*)d_in[0];   // y_pr  (16,2,512,512)
    // d_in[1] = y_gt (unused by the reference)
    const float* img  = (const float*)d_in[2];   // image (16,3,512,512)
    const int*   icls = (const int*)d_in[3];     // image_class (16,)
    float* out = (float*)d_out;

    zero_out_kernel<<<1, 32>>>(out);
    dim3 grid(GRIDX, BB);
    crf_loss_kernel<<<grid, NTHR>>>(ypr, img, icls, out);
}

// round 17
// speedup vs baseline: 1.1805x; 1.0175x over previous
#include <cuda_runtime.h>

#define HH 512
#define WW 512
#define BB 16
#define HW (HH * WW)
#define RPB 2
#define GRIDX (HH / RPB)      // 256
#define NTHR  128
#define FULLM 0xffffffffu

__device__ __forceinline__ float ex2f(float x) {
    float r; asm("ex2.approx.f32 %0, %1;" : "=f"(r) : "f"(x)); return r;
}

// acc += (ex2(d2*C2E)*wxy - eps) * (ya-yb)^2   [mul + fma tail]
__device__ __forceinline__ void shift_term(float& acc,
                                           float a0, float a1, float a2,
                                           float b0, float b1, float b2,
                                           float ya, float yb, float wxy) {
    const float C2E = -32.059889797532520f;   // -log2(e)/(2*0.15^2)
    float dx0 = a0 - b0, dx1 = a1 - b1, dx2 = a2 - b2;
    float d2 = dx0 * dx0;
    d2 = fmaf(dx1, dx1, d2);
    d2 = fmaf(dx2, dx2, d2);
    float e = ex2f(d2 * C2E);
    float m = fmaf(e, wxy, -0.01f);           // SUB_EPS
    float dy = ya - yb;
    float t = m * dy;
    acc = fmaf(t, dy, acc);
}

__global__ void __launch_bounds__(NTHR, 9)
crf_loss_kernel(const float* __restrict__ ypr,
                const float* __restrict__ img,
                const int*   __restrict__ icls,
                float* __restrict__ out)
{
    const int b = blockIdx.y;
    if (__ldg(icls + b) == 0) return;          // sel == 0: no contribution

    const int tid  = threadIdx.x;
    const int lane = tid & 31;
    const int w0   = tid << 2;                 // 4 px/thread, 128 thr = full row
    const int r0   = blockIdx.x * RPB;

    const float* Y = ypr + (size_t)(2 * b + 1) * HW;
    const float* I = img + (size_t)(3 * b)     * HW;   // planes +0, +HW, +2*HW

    const bool lastLane = (lane == 31);
    const bool hasR = (w0 + 4 < WW);           // false only tid 127

    const float WXY1 = 0.60653065971263342f;   // exp(-0.5)
    const float WXY2 = 0.36787944117144233f;   // exp(-1.0)

    // ---- prologue: row r0 + right halo ----
    float cy[4], ca[4], cb[4], cc[4];
    float cyR, caR, cbR, ccR;
    {
        const int off = r0 * WW + w0;
        float4 t;
        t = __ldg((const float4*)(Y + off));          cy[0]=t.x; cy[1]=t.y; cy[2]=t.z; cy[3]=t.w;
        t = __ldg((const float4*)(I + off));          ca[0]=t.x; ca[1]=t.y; ca[2]=t.z; ca[3]=t.w;
        t = __ldg((const float4*)(I + off + HW));     cb[0]=t.x; cb[1]=t.y; cb[2]=t.z; cb[3]=t.w;
        t = __ldg((const float4*)(I + off + 2*HW));   cc[0]=t.x; cc[1]=t.y; cc[2]=t.z; cc[3]=t.w;
        cyR = __shfl_down_sync(FULLM, cy[0], 1);
        caR = __shfl_down_sync(FULLM, ca[0], 1);
        cbR = __shfl_down_sync(FULLM, cb[0], 1);
        ccR = __shfl_down_sync(FULLM, cc[0], 1);
        if (lastLane && hasR) {
            cyR = __ldg(Y + off + 4);
            caR = __ldg(I + off + 4);
            cbR = __ldg(I + off + 4 + HW);
            ccR = __ldg(I + off + 4 + 2*HW);
        }
    }

    float acc = 0.0f;

#pragma unroll
    for (int rr = 0; rr < RPB; rr++) {
        const int r = r0 + rr;
        const bool haveDown = (r + 1 < HH);    // uniform across block
        const int off = (r + 1) * WW + w0;

        // ---- STEP 1: issue all next-row loads ----
        float ny[4], na[4], nb[4], nc[4];
        if (haveDown) {
            float4 t;
            t = __ldg((const float4*)(Y + off));        ny[0]=t.x; ny[1]=t.y; ny[2]=t.z; ny[3]=t.w;
            t = __ldg((const float4*)(I + off));        na[0]=t.x; na[1]=t.y; na[2]=t.z; na[3]=t.w;
            t = __ldg((const float4*)(I + off + HW));   nb[0]=t.x; nb[1]=t.y; nb[2]=t.z; nb[3]=t.w;
            t = __ldg((const float4*)(I + off + 2*HW)); nc[0]=t.x; nc[1]=t.y; nc[2]=t.z; nc[3]=t.w;
        } else {
#pragma unroll
            for (int k = 0; k < 4; k++) { ny[k]=0.f; na[k]=0.f; nb[k]=0.f; nc[k]=0.f; }
        }

        // ---- STEP 2: horizontal shift (0,1) on CURRENT row (independent) ----
#pragma unroll
        for (int k = 0; k < 3; k++)
            shift_term(acc, ca[k], cb[k], cc[k],
                       ca[k+1], cb[k+1], cc[k+1],
                       cy[k], cy[k+1], WXY1);
        if (hasR)
            shift_term(acc, ca[3], cb[3], cc[3], caR, cbR, ccR,
                       cy[3], cyR, WXY1);

        float nyR = 0.f, naR = 0.f, nbR = 0.f, ncR = 0.f;
        if (haveDown) {
            // ---- STEP 3: down-shuffles only (right halos of next row) ----
            nyR = __shfl_down_sync(FULLM, ny[0], 1);
            naR = __shfl_down_sync(FULLM, na[0], 1);
            nbR = __shfl_down_sync(FULLM, nb[0], 1);
            ncR = __shfl_down_sync(FULLM, nc[0], 1);
            if (lastLane && hasR) {
                nyR = __ldg(Y + off + 4);
                naR = __ldg(I + off + 4);
                nbR = __ldg(I + off + 4 + HW);
                ncR = __ldg(I + off + 4 + 2*HW);
            }

            // ---- STEP 4: vertical terms ----
            // shift (1,0)
#pragma unroll
            for (int k = 0; k < 4; k++)
                shift_term(acc, ca[k], cb[k], cc[k],
                           na[k], nb[k], nc[k],
                           cy[k], ny[k], WXY1);
            // shift (1,1)
#pragma unroll
            for (int k = 0; k < 3; k++)
                shift_term(acc, ca[k], cb[k], cc[k],
                           na[k+1], nb[k+1], nc[k+1],
                           cy[k], ny[k+1], WXY2);
            if (hasR)
                shift_term(acc, ca[3], cb[3], cc[3], naR, nbR, ncR,
                           cy[3], nyR, WXY2);
            // shift (1,-1): interior pairs (own data)
#pragma unroll
            for (int k = 1; k < 4; k++)
                shift_term(acc, ca[k], cb[k], cc[k],
                           na[k-1], nb[k-1], nc[k-1],
                           cy[k], ny[k-1], WXY2);
            // shift (1,-1) boundary pair (cur[w0+4], next[w0+3]) reassigned to
            // THIS lane: cur halo (c*R) vs own n*[3]. No up-shuffles needed.
            if (hasR)
                shift_term(acc, caR, cbR, ccR,
                           na[3], nb[3], nc[3],
                           cyR, ny[3], WXY2);
        }

        // ---- roll next -> current ----
#pragma unroll
        for (int k = 0; k < 4; k++) { cy[k]=ny[k]; ca[k]=na[k]; cb[k]=nb[k]; cc[k]=nc[k]; }
        cyR = nyR; caR = naR; cbR = nbR; ccR = ncR;
    }

    // ---- block reduction ----
#pragma unroll
    for (int o = 16; o > 0; o >>= 1)
        acc += __shfl_down_sync(FULLM, acc, o);

    __shared__ float sm[NTHR / 32];
    if (lane == 0) sm[tid >> 5] = acc;
    __syncthreads();
    if (tid == 0) {
        float v = sm[0] + sm[1] + sm[2] + sm[3];
        const float SCALE = 1.0f / 16777216.0f;    // 1/(H*W*B*4), WEIGHT=1
        atomicAdd(out, v * SCALE);
    }
}

__global__ void zero_out_kernel(float* out) {
    out[0] = 0.0f;
}

extern "C" void kernel_launch(void* const* d_in, const int* in_sizes, int n_in,
                              void* d_out, int out_size) {
    const float* ypr  = (const float*)d_in[0];   // y_pr  (16,2,512,512)
    // d_in[1] = y_gt (unused by the reference)
    const float* img  = (const float*)d_in[2];   // image (16,3,512,512)
    const int*   icls = (const int*)d_in[3];     // image_class (16,)
    float* out = (float*)d_out;

    zero_out_kernel<<<1, 1>>>(out);
    dim3 grid(GRIDX, BB);
    crf_loss_kernel<<<grid, NTHR>>>(ypr, img, icls, out);
}